// round 2
// baseline (speedup 1.0000x reference)
#include <cuda_runtime.h>

// BinsChamferLoss: n=16, d=128, h=192, w=256.
// out[b] = (loss1[b] + loss2[b]) / sum(valid_mask)   (count summed over ALL batches)
//   g = valid ? max(t, bins[b][0]) : bins[b][0]
//   loss1[b] = sum_pixels min_bins |g - bin|          (binary search, bins sorted)
//   loss2[b] = sum_bins  min_pixels |g - bin|         (per-segment pixel min/max +
//                                                      prefix-max / suffix-min)
// valid_mask arrives as int32 (harness has no bool dtype).

#define NB   16
#define DB   128
#define HW   49152           // 192*256
#define BPB  24              // blocks per batch
#define PPB  (HW / BPB)      // 2048 pixels per block
#define TH   256
#define NSEG (DB + 1)        // segment s in [1,128]; slot 0 unused
#define INF_BITS 0x7F800000

// Scratch (no cudaMalloc allowed).
__device__ float        g_loss1[NB];
__device__ unsigned int g_count;
__device__ int          g_pmax[NB * NSEG];   // positive floats as ints; -1 = empty
__device__ int          g_pmin[NB * NSEG];   // INF_BITS = empty

__global__ void bcl_init() {
    int t = blockIdx.x * blockDim.x + threadIdx.x;
    if (t < NB) g_loss1[t] = 0.0f;
    if (t == 0) g_count = 0u;
    if (t < NB * NSEG) { g_pmax[t] = -1; g_pmin[t] = INF_BITS; }
}

__global__ __launch_bounds__(TH) void bcl_main(const float* __restrict__ bins,
                                               const float* __restrict__ tdm,
                                               const int* __restrict__ mask) {
    const int batch = blockIdx.x / BPB;
    const int blk   = blockIdx.x % BPB;
    const int tid   = threadIdx.x;

    __shared__ float sb[DB + 1];       // bins, padded with +inf
    __shared__ int   spmax[NSEG];
    __shared__ int   spmin[NSEG];

    if (tid < DB)   sb[tid] = bins[batch * DB + tid];
    if (tid == DB)  sb[DB]  = __int_as_float(INF_BITS);
    for (int i = tid; i < NSEG; i += TH) { spmax[i] = -1; spmin[i] = INF_BITS; }
    __syncthreads();

    const float b0 = sb[0];
    float loss1 = 0.0f;
    unsigned int cnt = 0;

    const int base = batch * HW + blk * PPB;
    const float4* t4 = (const float4*)(tdm + base);
    const int4*   m4 = (const int4*)(mask + base);

    #pragma unroll
    for (int it = 0; it < PPB / (4 * TH); it++) {       // 2 iterations
        const int i = it * TH + tid;
        const float4 tv = t4[i];
        const int4   mv = m4[i];
        const float gv[4] = {tv.x, tv.y, tv.z, tv.w};
        const int   mk[4] = {mv.x, mv.y, mv.z, mv.w};
        #pragma unroll
        for (int k = 0; k < 4; k++) {
            const float g = mk[k] ? fmaxf(gv[k], b0) : b0;
            cnt += mk[k] ? 1u : 0u;
            // upper_bound: first index s with sb[s] > g.  s in [1,128] since sb[0] <= g.
            int lo = 0, hi = DB;
            #pragma unroll
            for (int bs = 0; bs < 8; bs++) {
                const int mid = (lo + hi) >> 1;
                if (sb[mid] <= g) lo = mid + 1; else hi = mid;
            }
            const int s = lo;
            loss1 += fminf(g - sb[s - 1], sb[s] - g);    // sb[128]=+inf handles s==128
            const int gi = __float_as_int(g);            // g > 0: int order == float order
            atomicMax(&spmax[s], gi);
            atomicMin(&spmin[s], gi);
        }
    }

    // block reduce loss1 & valid count
    #pragma unroll
    for (int off = 16; off; off >>= 1) {
        loss1 += __shfl_down_sync(0xFFFFFFFFu, loss1, off);
        cnt   += __shfl_down_sync(0xFFFFFFFFu, cnt,   off);
    }
    __shared__ float        wl[TH / 32];
    __shared__ unsigned int wc[TH / 32];
    if ((tid & 31) == 0) { wl[tid >> 5] = loss1; wc[tid >> 5] = cnt; }
    __syncthreads();
    if (tid == 0) {
        float L = 0.0f; unsigned int C = 0;
        #pragma unroll
        for (int w = 0; w < TH / 32; w++) { L += wl[w]; C += wc[w]; }
        atomicAdd(&g_loss1[batch], L);
        atomicAdd(&g_count, C);
    }

    // merge per-segment extrema to global
    for (int i = tid; i < NSEG; i += TH) {
        const int mx = spmax[i];
        if (mx != -1)       atomicMax(&g_pmax[batch * NSEG + i], mx);
        const int mn = spmin[i];
        if (mn != INF_BITS) atomicMin(&g_pmin[batch * NSEG + i], mn);
    }
}

__global__ void bcl_fin(const float* __restrict__ bins, float* __restrict__ out) {
    const int batch = blockIdx.x;
    const int j = threadIdx.x;                 // 128 threads = 128 bins

    __shared__ float smax[NSEG], smin[NSEG], pref[NSEG], suf[NSEG];
    __shared__ float sb[DB];

    sb[j] = bins[batch * DB + j];
    for (int i = j; i < NSEG; i += DB) {
        const int mx = g_pmax[batch * NSEG + i];
        smax[i] = (mx == -1) ? -1e30f : __int_as_float(mx);
        const int mn = g_pmin[batch * NSEG + i];
        smin[i] = (mn == INF_BITS) ? 1e30f : __int_as_float(mn);
    }
    __syncthreads();

    if (j == 0) {                              // 129-entry serial scans: negligible
        float r = -1e30f;
        for (int s = 0; s < NSEG; s++) { r = fmaxf(r, smax[s]); pref[s] = r; }
        float r2 = 1e30f;
        for (int s = NSEG - 1; s >= 0; s--) { r2 = fminf(r2, smin[s]); suf[s] = r2; }
    }
    __syncthreads();

    const float bj = sb[j];
    // below-set for bin j: segments 1..j (pixels < b_j); above-set: segments j+1..128
    const float mbelow = bj - pref[j];         // huge if empty (pref = -1e30)
    const float mabove = suf[j + 1] - bj;      // j+1 <= 128, suf[128] valid
    float v = fminf(mbelow, mabove);

    #pragma unroll
    for (int off = 16; off; off >>= 1) v += __shfl_down_sync(0xFFFFFFFFu, v, off);
    __shared__ float wsum[DB / 32];
    if ((j & 31) == 0) wsum[j >> 5] = v;
    __syncthreads();
    if (j == 0) {
        const float loss2 = wsum[0] + wsum[1] + wsum[2] + wsum[3];
        out[batch] = (loss2 + g_loss1[batch]) / (float)g_count;
    }
}

extern "C" void kernel_launch(void* const* d_in, const int* in_sizes, int n_in,
                              void* d_out, int out_size) {
    const float* bins = (const float*)d_in[0];
    const float* tdm  = (const float*)d_in[1];
    const int*   msk  = (const int*)d_in[2];
    float*       out  = (float*)d_out;

    bcl_init<<<(NB * NSEG + 255) / 256, 256>>>();
    bcl_main<<<NB * BPB, TH>>>(bins, tdm, msk);
    bcl_fin<<<NB, DB>>>(bins, out);
}